// round 3
// baseline (speedup 1.0000x reference)
#include <cuda_runtime.h>

// Problem constants (fixed shapes for this problem instance)
#define NN 50000
#define EE 800000
#define FF 128
#define HH 256
#define GG 512
#define TT 4

// ---------------- scratch (device globals: no allocation allowed) ----------
__device__ __align__(16) float g_dinv[NN];
__device__ __align__(16) float g_buf1[(size_t)NN * HH];   // GEMM outputs
__device__ __align__(16) float g_buf2[(size_t)NN * HH];   // agg / activations
__device__ __align__(16) float g_sums[GG * HH];
__device__ float g_cnt[GG];

// ---------------- degree / normalization ----------------------------------
__global__ void k_init_dinv() {
    int n = blockIdx.x * blockDim.x + threadIdx.x;
    if (n < NN) g_dinv[n] = 1.0f;   // self-loop contributes 1 to degree
}

__global__ void k_deg(const int* __restrict__ ei) {
    int e = blockIdx.x * blockDim.x + threadIdx.x;
    if (e < EE) atomicAdd(&g_dinv[ei[EE + e]], 1.0f);   // dst row
}

__global__ void k_fin_dinv() {
    int n = blockIdx.x * blockDim.x + threadIdx.x;
    if (n < NN) g_dinv[n] = rsqrtf(g_dinv[n]);          // deg >= 1 always
}

// ---------------- zero kernels ---------------------------------------------
__global__ void k_zero_buf2() {
    int i = blockIdx.x * blockDim.x + threadIdx.x;
    int stride = gridDim.x * blockDim.x;
    float4* p = (float4*)g_buf2;
    const int n4 = (NN * HH) / 4;
    for (int j = i; j < n4; j += stride) p[j] = make_float4(0.f, 0.f, 0.f, 0.f);
}

__global__ void k_zero_pool() {
    int i = blockIdx.x * blockDim.x + threadIdx.x;
    if (i < GG * HH) g_sums[i] = 0.0f;
    if (i < GG) g_cnt[i] = 0.0f;
}

// ---------------- SGEMM: C[M,256] = A[M,K] @ B[K,256] ----------------------
// 64x64 tile, TK=16, 256 threads, 4x4 microtile per thread.
template<int K, bool SRC_BUF2>
__global__ void k_gemm(const float* __restrict__ Aarg, const float* __restrict__ B) {
    const float* __restrict__ A = SRC_BUF2 ? (const float*)g_buf2 : Aarg;
    float* __restrict__ C = g_buf1;

    __shared__ float As[16][64];
    __shared__ float Bs[16][64];

    const int tid = threadIdx.x;
    const int tx = tid & 15;
    const int ty = tid >> 4;
    const int m0 = blockIdx.y * 64;
    const int n0 = blockIdx.x * 64;

    float acc[4][4];
#pragma unroll
    for (int i = 0; i < 4; i++)
#pragma unroll
        for (int j = 0; j < 4; j++) acc[i][j] = 0.0f;

    const int ra = tid >> 2;          // 0..63  (A tile row)
    const int ca = (tid & 3) * 4;     // 0,4,8,12 (A tile k-offset)
    const int rb = tid >> 4;          // 0..15  (B tile row)
    const int cb = (tid & 15) * 4;    // 0..60  (B tile col)

    for (int k0 = 0; k0 < K; k0 += 16) {
        float4 av;
        if (m0 + ra < NN)
            av = *(const float4*)(A + (size_t)(m0 + ra) * K + k0 + ca);
        else
            av = make_float4(0.f, 0.f, 0.f, 0.f);
        As[ca + 0][ra] = av.x;
        As[ca + 1][ra] = av.y;
        As[ca + 2][ra] = av.z;
        As[ca + 3][ra] = av.w;

        *(float4*)&Bs[rb][cb] = *(const float4*)(B + (size_t)(k0 + rb) * HH + n0 + cb);

        __syncthreads();
#pragma unroll
        for (int k = 0; k < 16; k++) {
            float4 a = *(const float4*)&As[k][ty * 4];
            float4 b = *(const float4*)&Bs[k][tx * 4];
            acc[0][0] += a.x * b.x; acc[0][1] += a.x * b.y; acc[0][2] += a.x * b.z; acc[0][3] += a.x * b.w;
            acc[1][0] += a.y * b.x; acc[1][1] += a.y * b.y; acc[1][2] += a.y * b.z; acc[1][3] += a.y * b.w;
            acc[2][0] += a.z * b.x; acc[2][1] += a.z * b.y; acc[2][2] += a.z * b.z; acc[2][3] += a.z * b.w;
            acc[3][0] += a.w * b.x; acc[3][1] += a.w * b.y; acc[3][2] += a.w * b.z; acc[3][3] += a.w * b.w;
        }
        __syncthreads();
    }

#pragma unroll
    for (int i = 0; i < 4; i++) {
        int m = m0 + ty * 4 + i;
        if (m < NN) {
            float4 v = make_float4(acc[i][0], acc[i][1], acc[i][2], acc[i][3]);
            *(float4*)(C + (size_t)m * HH + n0 + tx * 4) = v;
        }
    }
}

// ---------------- edge aggregation: agg[dst] += h[src] * norm --------------
// One warp per edge; float4 vector atomics (sm_90+) keep us on the LTS byte cap.
__global__ void k_agg(const int* __restrict__ ei) {
    int w = (blockIdx.x * blockDim.x + threadIdx.x) >> 5;
    int lane = threadIdx.x & 31;
    if (w >= EE) return;
    int s = ei[w];
    int d = ei[EE + w];
    float nrm = g_dinv[s] * g_dinv[d];
    const float4* __restrict__ hs = (const float4*)(g_buf1 + (size_t)s * HH);
    float4* __restrict__ ad = (float4*)(g_buf2 + (size_t)d * HH);
#pragma unroll
    for (int i = 0; i < 2; i++) {
        int c = lane + i * 32;       // 0..63 float4s = 256 floats
        float4 v = hs[c];
        atomicAdd(&ad[c], make_float4(v.x * nrm, v.y * nrm, v.z * nrm, v.w * nrm));
    }
}

// ---------------- self-loop + bias + relu (in place into buf2) -------------
__global__ void k_post(const float* __restrict__ b) {
    int n = blockIdx.x;
    int c = threadIdx.x;
    float di = g_dinv[n];
    size_t idx = (size_t)n * HH + c;
    float v = g_buf2[idx] + g_buf1[idx] * (di * di) + b[c];
    g_buf2[idx] = fmaxf(v, 0.0f);
}

// ---------------- global mean pool -----------------------------------------
__global__ void k_pool(const int* __restrict__ batch) {
    int n = blockIdx.x;
    int c = threadIdx.x;
    int g = batch[n];
    atomicAdd(&g_sums[g * HH + c], g_buf2[(size_t)n * HH + c]);
    if (c == 0) atomicAdd(&g_cnt[g], 1.0f);
}

// ---------------- MLP head: relu(concat(pooled, na) @ W3 + b3) @ W4 + b4 ---
__global__ void k_head(const float* __restrict__ na,
                       const float* __restrict__ W3, const float* __restrict__ b3,
                       const float* __restrict__ W4, const float* __restrict__ b4,
                       float* __restrict__ out) {
    int g = blockIdx.x;
    int j = threadIdx.x;   // 32 threads, one per hidden unit
    __shared__ float zsh[32];

    float inv = 1.0f / fmaxf(g_cnt[g], 1.0f);
    float acc = b3[j];
#pragma unroll 8
    for (int k = 0; k < HH; k++)
        acc += (g_sums[g * HH + k] * inv) * W3[k * 32 + j];
    acc += na[g] * W3[HH * 32 + j];   // num_atoms feature (row 256 of W3)
    zsh[j] = fmaxf(acc, 0.0f);
    __syncthreads();

    if (j < TT) {
        float o = b4[j];
#pragma unroll
        for (int t = 0; t < 32; t++) o += zsh[t] * W4[t * TT + j];
        out[g * TT + j] = o;
    }
}

// ---------------- launch ----------------------------------------------------
extern "C" void kernel_launch(void* const* d_in, const int* in_sizes, int n_in,
                              void* d_out, int out_size) {
    const float* x     = (const float*)d_in[0];
    const int*   ei    = (const int*)  d_in[1];
    const int*   batch = (const int*)  d_in[2];
    const float* na    = (const float*)d_in[3];
    const float* W1    = (const float*)d_in[4];
    const float* b1    = (const float*)d_in[5];
    const float* W2    = (const float*)d_in[6];
    const float* b2    = (const float*)d_in[7];
    const float* W3    = (const float*)d_in[8];
    const float* b3    = (const float*)d_in[9];
    const float* W4    = (const float*)d_in[10];
    const float* b4    = (const float*)d_in[11];
    float* out = (float*)d_out;

    // degree -> dinv
    k_init_dinv<<<(NN + 255) / 256, 256>>>();
    k_deg<<<(EE + 255) / 256, 256>>>(ei);
    k_fin_dinv<<<(NN + 255) / 256, 256>>>();

    dim3 gemm_grid(HH / 64, (NN + 63) / 64);

    // Layer 1: h = x @ W1 ; agg ; relu(agg + selfloop + b1)
    k_zero_buf2<<<1024, 256>>>();
    k_gemm<FF, false><<<gemm_grid, 256>>>(x, W1);
    k_agg<<<((size_t)EE * 32 + 255) / 256, 256>>>(ei);
    k_post<<<NN, 256>>>(b1);

    // Layer 2: h = a1 @ W2 ; agg ; relu(agg + selfloop + b2)
    k_gemm<HH, true><<<gemm_grid, 256>>>(nullptr, W2);
    k_zero_buf2<<<1024, 256>>>();
    k_agg<<<((size_t)EE * 32 + 255) / 256, 256>>>(ei);
    k_post<<<NN, 256>>>(b2);

    // Pool + head
    k_zero_pool<<<(GG * HH + 255) / 256, 256>>>();
    k_pool<<<NN, 256>>>(batch);
    k_head<<<GG, 32>>>(na, W3, b3, W4, b4, out);
}